// round 4
// baseline (speedup 1.0000x reference)
#include <cuda_runtime.h>
#include <cuda_bf16.h>
#include <cstdint>

// Problem constants
#define BB 2
#define SS 2048
#define DD 1024
#define HH 16
#define HD 64
#define MROWS (BB*SS)          // 4096
#define X_ELEMS (BB*SS*DD)     // 4194304
#define ATT_ELEMS (BB*HH*SS*SS)// 134217728

// ---------------- scratch (device globals: allocation-free) ----------------
__device__ float g_Q[MROWS*DD];    // [B*H][S][HD]
__device__ float g_K[MROWS*DD];    // [B*H][S][HD]
__device__ float g_V[MROWS*DD];    // [B*H][S][HD]
__device__ float g_ctx[MROWS*DD];  // [B][S][D]
__device__ float g_rsum[BB*HH*SS]; // softmax row sums

// ---------------- packed f32x2 helpers (Blackwell FFMA2 path) ----------------
__device__ __forceinline__ unsigned long long pk2(float lo, float hi) {
    unsigned long long r;
    asm("mov.b64 %0, {%1, %2};" : "=l"(r) : "f"(lo), "f"(hi));
    return r;
}
__device__ __forceinline__ void fma2(unsigned long long &d,
                                     unsigned long long a,
                                     unsigned long long b) {
    asm("fma.rn.f32x2 %0, %1, %2, %0;" : "+l"(d) : "l"(a), "l"(b));
}
__device__ __forceinline__ float2 upk(unsigned long long v) {
    float2 f;
    asm("mov.b64 {%0, %1}, %2;" : "=f"(f.x), "=f"(f.y) : "l"(v));
    return f;
}

// ---------------- SGEMM: C[m][n] = sum_k A[m][k]*W[n][k] + bias[n] ----------
// M=4096, N=1024, K=1024. 128x128 block, BK=8, 256 threads, 8x8 micro-tile
// mode 0: scatter to [B*H][S][HD] (QKV). mode 1: plain [M][N] row-major (O).
__global__ __launch_bounds__(256, 2)
void sgemm128(const float* __restrict__ A, const float* __restrict__ W,
              const float* __restrict__ bias, float* __restrict__ out, int mode)
{
    const int K = 1024;
    __shared__ float As[8][128];
    __shared__ float Bs[8][128];

    int tid  = threadIdx.x;
    int m0   = blockIdx.y << 7;
    int n0   = blockIdx.x << 7;
    int lrow = tid >> 1;
    int lseg = (tid & 1) << 2;
    int tx   = tid & 15, ty = tid >> 4;
    int ra   = ty << 2,  cb = tx << 2;

    const float* Ag = A + (size_t)(m0 + lrow) * K + lseg;
    const float* Wg = W + (size_t)(n0 + lrow) * K + lseg;

    unsigned long long acc[8][4];
#pragma unroll
    for (int i = 0; i < 8; i++)
#pragma unroll
        for (int j = 0; j < 4; j++) acc[i][j] = 0ull;

    float4 av = *(const float4*)Ag;
    float4 wv = *(const float4*)Wg;

    for (int k0 = 0; k0 < K; k0 += 8) {
        __syncthreads();
        As[lseg+0][lrow] = av.x; As[lseg+1][lrow] = av.y;
        As[lseg+2][lrow] = av.z; As[lseg+3][lrow] = av.w;
        Bs[lseg+0][lrow] = wv.x; Bs[lseg+1][lrow] = wv.y;
        Bs[lseg+2][lrow] = wv.z; Bs[lseg+3][lrow] = wv.w;
        __syncthreads();
        if (k0 + 8 < K) {               // prefetch next tile into registers
            av = *(const float4*)(Ag + k0 + 8);
            wv = *(const float4*)(Wg + k0 + 8);
        }
#pragma unroll
        for (int kk = 0; kk < 8; kk++) {
            float af[8];
            *(float4*)(af)     = *(const float4*)&As[kk][ra];
            *(float4*)(af + 4) = *(const float4*)&As[kk][64 + ra];
            unsigned long long b2[4];
            *(ulonglong2*)(b2)     = *(const ulonglong2*)&Bs[kk][cb];
            *(ulonglong2*)(b2 + 2) = *(const ulonglong2*)&Bs[kk][64 + cb];
#pragma unroll
            for (int i = 0; i < 8; i++) {
                unsigned long long ad = pk2(af[i], af[i]);
                fma2(acc[i][0], ad, b2[0]);
                fma2(acc[i][1], ad, b2[1]);
                fma2(acc[i][2], ad, b2[2]);
                fma2(acc[i][3], ad, b2[3]);
            }
        }
    }

    // epilogue
#pragma unroll
    for (int i = 0; i < 8; i++) {
        int r = m0 + ((i < 4) ? (ra + i) : (64 + ra + i - 4));
#pragma unroll
        for (int half = 0; half < 2; half++) {
            int c = n0 + (half ? (64 + cb) : cb);
            float2 p0 = upk(acc[i][half * 2 + 0]);
            float2 p1 = upk(acc[i][half * 2 + 1]);
            float4 v;
            v.x = p0.x + bias[c + 0];
            v.y = p0.y + bias[c + 1];
            v.z = p1.x + bias[c + 2];
            v.w = p1.y + bias[c + 3];
            if (mode == 0) {
                int b = r >> 11, s = r & 2047;
                int h = c >> 6,  hd = c & 63;
                *(float4*)&out[(((size_t)(b * HH + h) * SS) + s) * HD + hd] = v;
            } else {
                *(float4*)&out[(size_t)r * DD + c] = v;
            }
        }
    }
}

// ---------------- fused attention: scores -> exp -> attn write + PV ---------
// One block = one (b,h) x 64 q-rows. Loops k in 64-tiles.
// Writes UNNORMALIZED exp(score) to attn (normalized by attn_norm later),
// accumulates row sums, writes ctx = (P@V)/rowsum.
__global__ __launch_bounds__(256, 2)
void attn_fused(const float* __restrict__ Q, const float* __restrict__ Kt,
                const float* __restrict__ V, const int* __restrict__ mask,
                float* __restrict__ attn, float* __restrict__ ctx,
                float* __restrict__ rsum)
{
    extern __shared__ float sm[];
    float* Qs = sm;                  // [64][64]  [q][d]
    float* Ks = sm + 4096;           // [64][68]  [d][k] transposed, pad 68
    float* Vs = sm + 4096 + 4352;    // [64][64]  [k][d]
    float* Ps = Vs + 4096;           // [64][64]  [q][k]
    float* ls = Ps + 4096;           // [64]

    int tid = threadIdx.x, tx = tid & 15, ty = tid >> 4;
    int bh  = blockIdx.y;
    int b   = bh >> 4;
    int q0  = blockIdx.x << 6;

    // load Q tile (64x64), coalesced
#pragma unroll
    for (int i = 0; i < 4; i++) {
        int r = ty + (i << 4);
        *(float4*)&Qs[r * 64 + (tx << 2)] =
            *(const float4*)&Q[((size_t)bh * SS + q0 + r) * HD + (tx << 2)];
    }
    if (tid < 64) ls[tid] = 0.f;

    unsigned long long cacc[4][2];
#pragma unroll
    for (int i = 0; i < 4; i++) { cacc[i][0] = 0ull; cacc[i][1] = 0ull; }

    for (int kt = 0; kt < SS / 64; kt++) {
        int k0 = kt << 6;
        __syncthreads();   // protect Ks/Vs/Ps reuse from previous iteration
        // load K tile transposed [d][k] (pad 68), V tile plain [k][d]
#pragma unroll
        for (int i = 0; i < 4; i++) {
            int r = ty + (i << 4);
            int c = tx << 2;
            float4 kv = *(const float4*)&Kt[((size_t)bh * SS + k0 + r) * HD + c];
            Ks[(c + 0) * 68 + r] = kv.x;
            Ks[(c + 1) * 68 + r] = kv.y;
            Ks[(c + 2) * 68 + r] = kv.z;
            Ks[(c + 3) * 68 + r] = kv.w;
            *(float4*)&Vs[r * 64 + c] =
                *(const float4*)&V[((size_t)bh * SS + k0 + r) * HD + c];
        }
        __syncthreads();

        // scores: S[q][k] = sum_d Qs[q][d] * Ks[d][k]
        unsigned long long sacc[4][2];
#pragma unroll
        for (int i = 0; i < 4; i++) { sacc[i][0] = 0ull; sacc[i][1] = 0ull; }
#pragma unroll 8
        for (int d = 0; d < 64; d++) {
            unsigned long long b2[2];
            *(ulonglong2*)b2 = *(const ulonglong2*)&Ks[d * 68 + (tx << 2)];
#pragma unroll
            for (int i = 0; i < 4; i++) {
                float a = Qs[(ty * 4 + i) * 64 + d];
                unsigned long long ad = pk2(a, a);
                fma2(sacc[i][0], ad, b2[0]);
                fma2(sacc[i][1], ad, b2[1]);
            }
        }

        // exp (max-free: |score| stays < ~8 sigma, fp32-safe), mask,
        // write unnormalized attn, stage Ps, accumulate row sums
        int kb = k0 + (tx << 2);
        const int* mrow = mask + b * SS;
        float mj0 = mrow[kb + 0] ? 1.f : 0.f;
        float mj1 = mrow[kb + 1] ? 1.f : 0.f;
        float mj2 = mrow[kb + 2] ? 1.f : 0.f;
        float mj3 = mrow[kb + 3] ? 1.f : 0.f;
#pragma unroll
        for (int i = 0; i < 4; i++) {
            float2 s0 = upk(sacc[i][0]);
            float2 s1 = upk(sacc[i][1]);
            float4 p;
            p.x = mj0 * __expf(s0.x * 0.125f);
            p.y = mj1 * __expf(s0.y * 0.125f);
            p.z = mj2 * __expf(s1.x * 0.125f);
            p.w = mj3 * __expf(s1.y * 0.125f);
            *(float4*)&Ps[(ty * 4 + i) * 64 + (tx << 2)] = p;
            *(float4*)&attn[((size_t)bh * SS + q0 + ty * 4 + i) * SS + kb] = p;
            float rs = p.x + p.y + p.z + p.w;
            rs += __shfl_xor_sync(0xffffffffu, rs, 1);
            rs += __shfl_xor_sync(0xffffffffu, rs, 2);
            rs += __shfl_xor_sync(0xffffffffu, rs, 4);
            rs += __shfl_xor_sync(0xffffffffu, rs, 8);
            if (tx == 0) ls[ty * 4 + i] += rs;   // unique writer per row
        }
        __syncthreads();

        // PV: ctx[q][d] += sum_k Ps[q][k] * Vs[k][d]
#pragma unroll 8
        for (int k = 0; k < 64; k++) {
            unsigned long long b2[2];
            *(ulonglong2*)b2 = *(const ulonglong2*)&Vs[k * 64 + (tx << 2)];
#pragma unroll
            for (int i = 0; i < 4; i++) {
                float a = Ps[(ty * 4 + i) * 64 + k];
                unsigned long long ad = pk2(a, a);
                fma2(cacc[i][0], ad, b2[0]);
                fma2(cacc[i][1], ad, b2[1]);
            }
        }
    }
    __syncthreads();

    // epilogue: ctx /= rowsum, scatter to [B][S][D]; export row sums
    int h = bh & 15;
#pragma unroll
    for (int i = 0; i < 4; i++) {
        float inv = 1.0f / ls[ty * 4 + i];
        float2 c0 = upk(cacc[i][0]);
        float2 c1 = upk(cacc[i][1]);
        float4 v;
        v.x = c0.x * inv; v.y = c0.y * inv;
        v.z = c1.x * inv; v.w = c1.y * inv;
        int s_ = q0 + ty * 4 + i;
        *(float4*)&ctx[((size_t)(b * SS + s_)) * DD + h * HD + (tx << 2)] = v;
    }
    if (tid < 64) rsum[(size_t)bh * SS + q0 + tid] = ls[tid];
}

// ---------------- normalize attn by row sums (pure bandwidth) ---------------
__global__ void attn_norm(float* __restrict__ attn, const float* __restrict__ rsum)
{
    size_t i = (size_t)blockIdx.x * blockDim.x + threadIdx.x;  // one float4 each
    float4* a = reinterpret_cast<float4*>(attn);
    size_t row = i >> 9;               // 2048 floats = 512 float4 per row
    float inv = 1.0f / __ldg(&rsum[row]);
    float4 v = a[i];
    v.x *= inv; v.y *= inv; v.z *= inv; v.w *= inv;
    a[i] = v;
}

// ---------------- launch ----------------
extern "C" void kernel_launch(void* const* d_in, const int* in_sizes, int n_in,
                              void* d_out, int out_size)
{
    const float* q    = (const float*)d_in[0];
    const float* k    = (const float*)d_in[1];
    const float* v    = (const float*)d_in[2];
    const int*   mask = (const int*)  d_in[3];
    const float* Wq   = (const float*)d_in[4];
    const float* bq   = (const float*)d_in[5];
    const float* Wk   = (const float*)d_in[6];
    const float* bk   = (const float*)d_in[7];
    const float* Wv   = (const float*)d_in[8];
    const float* bv   = (const float*)d_in[9];
    const float* Wo   = (const float*)d_in[10];
    const float* bo   = (const float*)d_in[11];

    float* outx = (float*)d_out;
    float* attn = outx + X_ELEMS;

    float *pQ, *pK, *pV, *pC, *pR;
    cudaGetSymbolAddress((void**)&pQ, g_Q);
    cudaGetSymbolAddress((void**)&pK, g_K);
    cudaGetSymbolAddress((void**)&pV, g_V);
    cudaGetSymbolAddress((void**)&pC, g_ctx);
    cudaGetSymbolAddress((void**)&pR, g_rsum);

    const int ATT_SMEM = (4096 + 4352 + 4096 + 4096 + 64) * 4;  // 66816 B
    cudaFuncSetAttribute(attn_fused,
                         cudaFuncAttributeMaxDynamicSharedMemorySize, ATT_SMEM);

    dim3 gg(DD / 128, MROWS / 128), bt(256);
    sgemm128<<<gg, bt>>>(q, Wq, bq, pQ, 0);
    sgemm128<<<gg, bt>>>(k, Wk, bk, pK, 0);
    sgemm128<<<gg, bt>>>(v, Wv, bv, pV, 0);

    attn_fused<<<dim3(SS / 64, BB * HH), 256, ATT_SMEM>>>(pQ, pK, pV, mask,
                                                          attn, pC, pR);
    attn_norm<<<ATT_ELEMS / 4 / 256, 256>>>(attn, pR);

    sgemm128<<<gg, bt>>>(pC, Wo, bo, outx, 1);
}

// round 5
// speedup vs baseline: 1.0092x; 1.0092x over previous
#include <cuda_runtime.h>
#include <cuda_bf16.h>
#include <cstdint>

// Problem constants
#define BB 2
#define SS 2048
#define DD 1024
#define HH 16
#define HD 64
#define MROWS (BB*SS)          // 4096
#define X_ELEMS (BB*SS*DD)     // 4194304
#define ATT_ELEMS (BB*HH*SS*SS)// 134217728

// ---------------- scratch (device globals: allocation-free) ----------------
__device__ float g_Q[MROWS*DD];    // [B*H][S][HD]
__device__ float g_K[MROWS*DD];    // [B*H][S][HD]
__device__ float g_V[MROWS*DD];    // [B*H][S][HD]
__device__ float g_ctx[MROWS*DD];  // [B][S][D]
__device__ float g_rsum[BB*HH*SS]; // softmax row sums

// ---------------- packed f32x2 helpers (Blackwell FFMA2 path) ----------------
__device__ __forceinline__ unsigned long long pk2(float lo, float hi) {
    unsigned long long r;
    asm("mov.b64 %0, {%1, %2};" : "=l"(r) : "f"(lo), "f"(hi));
    return r;
}
__device__ __forceinline__ void fma2(unsigned long long &d,
                                     unsigned long long a,
                                     unsigned long long b) {
    asm("fma.rn.f32x2 %0, %1, %2, %0;" : "+l"(d) : "l"(a), "l"(b));
}
__device__ __forceinline__ float2 upk(unsigned long long v) {
    float2 f;
    asm("mov.b64 {%0, %1}, %2;" : "=f"(f.x), "=f"(f.y) : "l"(v));
    return f;
}

// ---------------- SGEMM: C[m][n] = sum_k A[m][k]*W[n][k] + bias[n] ----------
// M=4096, N=1024, K=1024. 128x128 block, BK=8, 256 threads, 8x8 micro-tile
// mode 0: scatter to [B*H][S][HD] (QKV). mode 1: plain [M][N] row-major (O).
__global__ __launch_bounds__(256, 2)
void sgemm128(const float* __restrict__ A, const float* __restrict__ W,
              const float* __restrict__ bias, float* __restrict__ out, int mode)
{
    const int K = 1024;
    __shared__ float As[8][128];
    __shared__ float Bs[8][128];

    int tid  = threadIdx.x;
    int m0   = blockIdx.y << 7;
    int n0   = blockIdx.x << 7;
    int lrow = tid >> 1;
    int lseg = (tid & 1) << 2;
    int tx   = tid & 15, ty = tid >> 4;
    int ra   = ty << 2,  cb = tx << 2;

    const float* Ag = A + (size_t)(m0 + lrow) * K + lseg;
    const float* Wg = W + (size_t)(n0 + lrow) * K + lseg;

    unsigned long long acc[8][4];
#pragma unroll
    for (int i = 0; i < 8; i++)
#pragma unroll
        for (int j = 0; j < 4; j++) acc[i][j] = 0ull;

    float4 av = *(const float4*)Ag;
    float4 wv = *(const float4*)Wg;

    for (int k0 = 0; k0 < K; k0 += 8) {
        __syncthreads();
        As[lseg+0][lrow] = av.x; As[lseg+1][lrow] = av.y;
        As[lseg+2][lrow] = av.z; As[lseg+3][lrow] = av.w;
        Bs[lseg+0][lrow] = wv.x; Bs[lseg+1][lrow] = wv.y;
        Bs[lseg+2][lrow] = wv.z; Bs[lseg+3][lrow] = wv.w;
        __syncthreads();
        if (k0 + 8 < K) {               // prefetch next tile into registers
            av = *(const float4*)(Ag + k0 + 8);
            wv = *(const float4*)(Wg + k0 + 8);
        }
#pragma unroll
        for (int kk = 0; kk < 8; kk++) {
            float af[8];
            *(float4*)(af)     = *(const float4*)&As[kk][ra];
            *(float4*)(af + 4) = *(const float4*)&As[kk][64 + ra];
            unsigned long long b2[4];
            *(ulonglong2*)(b2)     = *(const ulonglong2*)&Bs[kk][cb];
            *(ulonglong2*)(b2 + 2) = *(const ulonglong2*)&Bs[kk][64 + cb];
#pragma unroll
            for (int i = 0; i < 8; i++) {
                unsigned long long ad = pk2(af[i], af[i]);
                fma2(acc[i][0], ad, b2[0]);
                fma2(acc[i][1], ad, b2[1]);
                fma2(acc[i][2], ad, b2[2]);
                fma2(acc[i][3], ad, b2[3]);
            }
        }
    }

    // epilogue
#pragma unroll
    for (int i = 0; i < 8; i++) {
        int r = m0 + ((i < 4) ? (ra + i) : (64 + ra + i - 4));
#pragma unroll
        for (int half = 0; half < 2; half++) {
            int c = n0 + (half ? (64 + cb) : cb);
            float2 p0 = upk(acc[i][half * 2 + 0]);
            float2 p1 = upk(acc[i][half * 2 + 1]);
            float4 v;
            v.x = p0.x + bias[c + 0];
            v.y = p0.y + bias[c + 1];
            v.z = p1.x + bias[c + 2];
            v.w = p1.y + bias[c + 3];
            if (mode == 0) {
                int b = r >> 11, s = r & 2047;
                int h = c >> 6,  hd = c & 63;
                *(float4*)&out[(((size_t)(b * HH + h) * SS) + s) * HD + hd] = v;
            } else {
                *(float4*)&out[(size_t)r * DD + c] = v;
            }
        }
    }
}

// ---------------- fused attention v2: 128q x 64k tile, 8x4 micro-tile ------
// One block = one (b,h) x 128 q-rows. Loops over k in 64-tiles.
// Writes UNNORMALIZED exp(score) to attn (normalized by attn_norm later),
// accumulates per-thread row sums in registers, writes ctx = (P@V)/rowsum.
//
// Thread map: tx = tid&15 (16 lanes -> 4 k or 4 d each), ty = tid>>4 (16 -> 8 q each)
// Scores: sacc[8 q][4 k]  (2 f32x2 each)    PV: cacc[8 q][4 d]
// Inner loops vectorized 4-wide: 12 LDS.128 per 64 FFMA2 (a-loads broadcast).
__global__ __launch_bounds__(256, 2)
void attn_fused(const float* __restrict__ Q, const float* __restrict__ Kt,
                const float* __restrict__ V, const int* __restrict__ mask,
                float* __restrict__ attn, float* __restrict__ ctx,
                float* __restrict__ rsum)
{
    extern __shared__ float sm[];
    float* Qs = sm;             // [128][64]  [q][d]
    float* Ks = sm + 8192;      // [64][68]   [d][k], pad 68 (16B-aligned rows)
    float* Vs = sm + 12544;     // [64][64]   [k][d]
    float* Ps = sm + 16640;     // [128][64]  [q][k]
    float* ls = sm + 24832;     // [128]

    int tid = threadIdx.x, tx = tid & 15, ty = tid >> 4;
    int bh  = blockIdx.y;
    int b   = bh >> 4, h = bh & 15;
    int q0  = blockIdx.x << 7;

    // load Q tile (128x64), coalesced
#pragma unroll
    for (int idx = tid; idx < 128 * 16; idx += 256) {
        int r = idx >> 4, c4 = (idx & 15) << 2;
        *(float4*)&Qs[r * 64 + c4] =
            *(const float4*)&Q[((size_t)bh * SS + q0 + r) * HD + c4];
    }

    unsigned long long cacc[8][2];
    float rsacc[8];
#pragma unroll
    for (int i = 0; i < 8; i++) {
        cacc[i][0] = 0ull; cacc[i][1] = 0ull; rsacc[i] = 0.f;
    }

    const int* mrow = mask + b * SS;

    for (int kt = 0; kt < SS / 64; kt++) {
        int k0 = kt << 6;
        __syncthreads();   // previous PV done before Ks/Vs overwrite
        // load K tile transposed [d][k] and V tile plain [k][d]
#pragma unroll
        for (int idx = tid; idx < 64 * 16; idx += 256) {
            int r = idx >> 4, c4 = (idx & 15) << 2;
            float4 kv = *(const float4*)&Kt[((size_t)bh * SS + k0 + r) * HD + c4];
            Ks[(c4 + 0) * 68 + r] = kv.x;
            Ks[(c4 + 1) * 68 + r] = kv.y;
            Ks[(c4 + 2) * 68 + r] = kv.z;
            Ks[(c4 + 3) * 68 + r] = kv.w;
            *(float4*)&Vs[r * 64 + c4] =
                *(const float4*)&V[((size_t)bh * SS + k0 + r) * HD + c4];
        }
        __syncthreads();

        // ---- scores: S[q][k] = sum_d Qs[q][d] * Ks[d][k] ----
        unsigned long long sacc[8][2];
#pragma unroll
        for (int i = 0; i < 8; i++) { sacc[i][0] = 0ull; sacc[i][1] = 0ull; }

#pragma unroll 2
        for (int d0 = 0; d0 < 64; d0 += 4) {
            float4 bv[4];
#pragma unroll
            for (int j = 0; j < 4; j++)
                bv[j] = *(const float4*)&Ks[(d0 + j) * 68 + (tx << 2)];
            float4 av[8];
#pragma unroll
            for (int qi = 0; qi < 8; qi++)
                av[qi] = *(const float4*)&Qs[(ty * 8 + qi) * 64 + d0];
#pragma unroll
            for (int j = 0; j < 4; j++) {
                const unsigned long long* bp =
                    reinterpret_cast<const unsigned long long*>(&bv[j]);
#pragma unroll
                for (int qi = 0; qi < 8; qi++) {
                    float a = reinterpret_cast<const float*>(&av[qi])[j];
                    unsigned long long ad = pk2(a, a);
                    fma2(sacc[qi][0], ad, bp[0]);
                    fma2(sacc[qi][1], ad, bp[1]);
                }
            }
        }

        // ---- exp (max-free: scores ~N(0,1) after /8, fp32-safe), mask,
        //      write unnormalized attn, stage Ps, accumulate row sums ----
        int kb = k0 + (tx << 2);
        float mj0 = mrow[kb + 0] ? 1.f : 0.f;
        float mj1 = mrow[kb + 1] ? 1.f : 0.f;
        float mj2 = mrow[kb + 2] ? 1.f : 0.f;
        float mj3 = mrow[kb + 3] ? 1.f : 0.f;
#pragma unroll
        for (int qi = 0; qi < 8; qi++) {
            float2 s0 = upk(sacc[qi][0]);
            float2 s1 = upk(sacc[qi][1]);
            float4 p;
            p.x = mj0 * __expf(s0.x * 0.125f);
            p.y = mj1 * __expf(s0.y * 0.125f);
            p.z = mj2 * __expf(s1.x * 0.125f);
            p.w = mj3 * __expf(s1.y * 0.125f);
            *(float4*)&Ps[(ty * 8 + qi) * 64 + (tx << 2)] = p;
            *(float4*)&attn[((size_t)bh * SS + q0 + ty * 8 + qi) * SS + kb] = p;
            rsacc[qi] += (p.x + p.y) + (p.z + p.w);
        }
        __syncthreads();   // Ps complete before PV reads

        // ---- PV: ctx[q][d] += sum_k Ps[q][k] * Vs[k][d] ----
#pragma unroll 2
        for (int kk = 0; kk < 64; kk += 4) {
            float4 bv[4];
#pragma unroll
            for (int j = 0; j < 4; j++)
                bv[j] = *(const float4*)&Vs[(kk + j) * 64 + (tx << 2)];
            float4 av[8];
#pragma unroll
            for (int qi = 0; qi < 8; qi++)
                av[qi] = *(const float4*)&Ps[(ty * 8 + qi) * 64 + kk];
#pragma unroll
            for (int j = 0; j < 4; j++) {
                const unsigned long long* bp =
                    reinterpret_cast<const unsigned long long*>(&bv[j]);
#pragma unroll
                for (int qi = 0; qi < 8; qi++) {
                    float a = reinterpret_cast<const float*>(&av[qi])[j];
                    unsigned long long ad = pk2(a, a);
                    fma2(cacc[qi][0], ad, bp[0]);
                    fma2(cacc[qi][1], ad, bp[1]);
                }
            }
        }
    }

    // ---- final row-sum reduction across tx (16 lanes within half-warp) ----
#pragma unroll
    for (int qi = 0; qi < 8; qi++) {
        float rs = rsacc[qi];
        rs += __shfl_xor_sync(0xffffffffu, rs, 1);
        rs += __shfl_xor_sync(0xffffffffu, rs, 2);
        rs += __shfl_xor_sync(0xffffffffu, rs, 4);
        rs += __shfl_xor_sync(0xffffffffu, rs, 8);
        if (tx == 0) ls[ty * 8 + qi] = rs;   // unique writer per row
    }
    __syncthreads();

    // ---- epilogue: ctx /= rowsum, scatter to [B][S][D]; export sums ----
#pragma unroll
    for (int qi = 0; qi < 8; qi++) {
        float inv = 1.0f / ls[ty * 8 + qi];
        float2 c0 = upk(cacc[qi][0]);
        float2 c1 = upk(cacc[qi][1]);
        float4 v;
        v.x = c0.x * inv; v.y = c0.y * inv;
        v.z = c1.x * inv; v.w = c1.y * inv;
        int s_ = q0 + ty * 8 + qi;
        *(float4*)&ctx[((size_t)(b * SS + s_)) * DD + h * HD + (tx << 2)] = v;
    }
    if (tid < 128) rsum[(size_t)bh * SS + q0 + tid] = ls[tid];
}

// ---------------- normalize attn by row sums (pure bandwidth) ---------------
__global__ void attn_norm(float* __restrict__ attn, const float* __restrict__ rsum)
{
    size_t i = (size_t)blockIdx.x * blockDim.x + threadIdx.x;  // one float4 each
    float4* a = reinterpret_cast<float4*>(attn);
    size_t row = i >> 9;               // 2048 floats = 512 float4 per row
    float inv = 1.0f / __ldg(&rsum[row]);
    float4 v = a[i];
    v.x *= inv; v.y *= inv; v.z *= inv; v.w *= inv;
    a[i] = v;
}

// ---------------- launch ----------------
extern "C" void kernel_launch(void* const* d_in, const int* in_sizes, int n_in,
                              void* d_out, int out_size)
{
    const float* q    = (const float*)d_in[0];
    const float* k    = (const float*)d_in[1];
    const float* v    = (const float*)d_in[2];
    const int*   mask = (const int*)  d_in[3];
    const float* Wq   = (const float*)d_in[4];
    const float* bq   = (const float*)d_in[5];
    const float* Wk   = (const float*)d_in[6];
    const float* bk   = (const float*)d_in[7];
    const float* Wv   = (const float*)d_in[8];
    const float* bv   = (const float*)d_in[9];
    const float* Wo   = (const float*)d_in[10];
    const float* bo   = (const float*)d_in[11];

    float* outx = (float*)d_out;
    float* attn = outx + X_ELEMS;

    float *pQ, *pK, *pV, *pC, *pR;
    cudaGetSymbolAddress((void**)&pQ, g_Q);
    cudaGetSymbolAddress((void**)&pK, g_K);
    cudaGetSymbolAddress((void**)&pV, g_V);
    cudaGetSymbolAddress((void**)&pC, g_ctx);
    cudaGetSymbolAddress((void**)&pR, g_rsum);

    // Qs 8192 + Ks 4352 + Vs 4096 + Ps 8192 + ls 128 = 24960 floats
    const int ATT_SMEM = 24960 * 4;   // 99840 B  (2 CTAs/SM)
    cudaFuncSetAttribute(attn_fused,
                         cudaFuncAttributeMaxDynamicSharedMemorySize, ATT_SMEM);

    dim3 gg(DD / 128, MROWS / 128), bt(256);
    sgemm128<<<gg, bt>>>(q, Wq, bq, pQ, 0);
    sgemm128<<<gg, bt>>>(k, Wk, bk, pK, 0);
    sgemm128<<<gg, bt>>>(v, Wv, bv, pV, 0);

    attn_fused<<<dim3(SS / 128, BB * HH), 256, ATT_SMEM>>>(pQ, pK, pV, mask,
                                                           attn, pC, pR);
    attn_norm<<<ATT_ELEMS / 4 / 256, 256>>>(attn, pR);

    sgemm128<<<gg, bt>>>(pC, Wo, bo, outx, 1);
}

// round 14
// speedup vs baseline: 1.4702x; 1.4568x over previous
#include <cuda_runtime.h>
#include <cuda_bf16.h>
#include <cstdint>

// Problem constants
#define BB 2
#define SS 2048
#define DD 1024
#define HH 16
#define HD 64
#define MROWS (BB*SS)          // 4096
#define X_ELEMS (BB*SS*DD)     // 4194304
#define ATT_ELEMS (BB*HH*SS*SS)// 134217728

// ---------------- scratch (device globals: allocation-free) ----------------
__device__ float g_ctx[MROWS*DD];  // [B][S][D] fp32 context (input to O proj)
__device__ __nv_bfloat16 g_Qh[MROWS*DD], g_Ql[MROWS*DD]; // [BH][S][HD]
__device__ __nv_bfloat16 g_Kh[MROWS*DD], g_Kl[MROWS*DD]; // [BH][S][HD]
__device__ __nv_bfloat16 g_Vh[MROWS*DD], g_Vl[MROWS*DD]; // [BH][S][HD]

// ---------------- packed f32x2 helpers (FFMA2 path, projections) -----------
__device__ __forceinline__ unsigned long long pk2(float lo, float hi) {
    unsigned long long r;
    asm("mov.b64 %0, {%1, %2};" : "=l"(r) : "f"(lo), "f"(hi));
    return r;
}
__device__ __forceinline__ void fma2(unsigned long long &d,
                                     unsigned long long a,
                                     unsigned long long b) {
    asm("fma.rn.f32x2 %0, %1, %2, %0;" : "+l"(d) : "l"(a), "l"(b));
}
__device__ __forceinline__ float2 upk(unsigned long long v) {
    float2 f;
    asm("mov.b64 {%0, %1}, %2;" : "=f"(f.x), "=f"(f.y) : "l"(v));
    return f;
}

// ---------------- mma.sync / ldmatrix helpers (baseline ISA, sm_80+) -------
__device__ __forceinline__ uint32_t smem_u32(const void* p) {
    uint32_t a;
    asm("{ .reg .u64 t; cvta.to.shared.u64 t, %1; cvt.u32.u64 %0, t; }"
        : "=r"(a) : "l"(p));
    return a;
}
#define LDSM4(r, a)                                                          \
    asm volatile("ldmatrix.sync.aligned.m8n8.x4.shared.b16 {%0,%1,%2,%3}, [%4];" \
        : "=r"((r)[0]), "=r"((r)[1]), "=r"((r)[2]), "=r"((r)[3]) : "r"(a) : "memory")
#define LDSM2(r, a)                                                          \
    asm volatile("ldmatrix.sync.aligned.m8n8.x2.shared.b16 {%0,%1}, [%2];"   \
        : "=r"((r)[0]), "=r"((r)[1]) : "r"(a) : "memory")
#define LDSM2T(r, a)                                                         \
    asm volatile("ldmatrix.sync.aligned.m8n8.x2.trans.shared.b16 {%0,%1}, [%2];" \
        : "=r"((r)[0]), "=r"((r)[1]) : "r"(a) : "memory")
#define MMA_BF16(c, a, b0, b1)                                               \
    asm volatile("mma.sync.aligned.m16n8k16.row.col.f32.bf16.bf16.f32 "      \
        "{%0,%1,%2,%3}, {%4,%5,%6,%7}, {%8,%9}, {%0,%1,%2,%3};"              \
        : "+f"((c)[0]), "+f"((c)[1]), "+f"((c)[2]), "+f"((c)[3])             \
        : "r"((a)[0]), "r"((a)[1]), "r"((a)[2]), "r"((a)[3]),                \
          "r"(b0), "r"(b1))

// hi/lo bf16 split of two floats -> packed bf16x2 words
__device__ __forceinline__ void split2(float a, float b, uint32_t &h, uint32_t &l) {
    __nv_bfloat162 hb = __floats2bfloat162_rn(a, b);
    float2 hf = __bfloat1622float2(hb);
    __nv_bfloat162 lb = __floats2bfloat162_rn(a - hf.x, b - hf.y);
    h = *reinterpret_cast<uint32_t*>(&hb);
    l = *reinterpret_cast<uint32_t*>(&lb);
}

// ---------------- SGEMM (FFMA2): projections --------------------------------
// mode 0: write bf16 hi/lo split, scattered to [B*H][S][HD] (QKV proj)
// mode 1: write fp32 plain [M][N] row-major (O proj)
__global__ __launch_bounds__(256, 2)
void sgemm128(const float* __restrict__ A, const float* __restrict__ W,
              const float* __restrict__ bias, float* __restrict__ out,
              __nv_bfloat16* __restrict__ outH, __nv_bfloat16* __restrict__ outL,
              int mode)
{
    const int K = 1024;
    __shared__ float As[8][128];
    __shared__ float Bs[8][128];

    int tid  = threadIdx.x;
    int m0   = blockIdx.y << 7;
    int n0   = blockIdx.x << 7;
    int lrow = tid >> 1;
    int lseg = (tid & 1) << 2;
    int tx   = tid & 15, ty = tid >> 4;
    int ra   = ty << 2,  cb = tx << 2;

    const float* Ag = A + (size_t)(m0 + lrow) * K + lseg;
    const float* Wg = W + (size_t)(n0 + lrow) * K + lseg;

    unsigned long long acc[8][4];
#pragma unroll
    for (int i = 0; i < 8; i++)
#pragma unroll
        for (int j = 0; j < 4; j++) acc[i][j] = 0ull;

    float4 av = *(const float4*)Ag;
    float4 wv = *(const float4*)Wg;

    for (int k0 = 0; k0 < K; k0 += 8) {
        __syncthreads();
        As[lseg+0][lrow] = av.x; As[lseg+1][lrow] = av.y;
        As[lseg+2][lrow] = av.z; As[lseg+3][lrow] = av.w;
        Bs[lseg+0][lrow] = wv.x; Bs[lseg+1][lrow] = wv.y;
        Bs[lseg+2][lrow] = wv.z; Bs[lseg+3][lrow] = wv.w;
        __syncthreads();
        if (k0 + 8 < K) {
            av = *(const float4*)(Ag + k0 + 8);
            wv = *(const float4*)(Wg + k0 + 8);
        }
#pragma unroll
        for (int kk = 0; kk < 8; kk++) {
            float af[8];
            *(float4*)(af)     = *(const float4*)&As[kk][ra];
            *(float4*)(af + 4) = *(const float4*)&As[kk][64 + ra];
            unsigned long long b2[4];
            *(ulonglong2*)(b2)     = *(const ulonglong2*)&Bs[kk][cb];
            *(ulonglong2*)(b2 + 2) = *(const ulonglong2*)&Bs[kk][64 + cb];
#pragma unroll
            for (int i = 0; i < 8; i++) {
                unsigned long long ad = pk2(af[i], af[i]);
                fma2(acc[i][0], ad, b2[0]);
                fma2(acc[i][1], ad, b2[1]);
                fma2(acc[i][2], ad, b2[2]);
                fma2(acc[i][3], ad, b2[3]);
            }
        }
    }

#pragma unroll
    for (int i = 0; i < 8; i++) {
        int r = m0 + ((i < 4) ? (ra + i) : (64 + ra + i - 4));
#pragma unroll
        for (int half = 0; half < 2; half++) {
            int c = n0 + (half ? (64 + cb) : cb);
            float2 p0 = upk(acc[i][half * 2 + 0]);
            float2 p1 = upk(acc[i][half * 2 + 1]);
            float4 v;
            v.x = p0.x + bias[c + 0];
            v.y = p0.y + bias[c + 1];
            v.z = p1.x + bias[c + 2];
            v.w = p1.y + bias[c + 3];
            if (mode == 0) {
                int b = r >> 11, s = r & 2047;
                int h = c >> 6,  hd = c & 63;
                size_t o = (((size_t)(b * HH + h) * SS) + s) * HD + hd;
                uint32_t h0, h1, l0, l1;
                split2(v.x, v.y, h0, l0);
                split2(v.z, v.w, h1, l1);
                *(uint2*)&outH[o] = make_uint2(h0, h1);
                *(uint2*)&outL[o] = make_uint2(l0, l1);
            } else {
                *(float4*)&out[(size_t)r * DD + c] = v;
            }
        }
    }
}

// ---------------- mma.sync fused attention ----------------------------------
// Per CTA: one (b,h), 128 q rows, 8 warps (16 q rows each), k loop 64-wide,
// NKT = SS/64 = 32 k-tiles (R8/R12 bug: was 16 -> half the sequence ignored).
// Two passes: pass 1 = exact row sums; pass 2 = normalized attn write + PV.
// bf16 hi/lo split (3 MMA products) for fp32-grade accuracy.
#define SOFF(row, ch) ((uint32_t)((row) * 128 + (((ch) ^ ((row) & 7)) << 4)))
#define O_QH 0
#define O_QL 16384
#define O_KH 32768
#define O_KL 40960
#define O_VH 49152
#define O_VL 57344
#define O_MSK 65536
#define ATT_SMEM (65536 + 256)
#define NKT (SS / 64)   // 32

__global__ __launch_bounds__(256, 2)
void attn_mma(const int* __restrict__ mask, float* __restrict__ attn)
{
    extern __shared__ char sm[];
    uint32_t sb = smem_u32(sm);

    int tid = threadIdx.x, w = tid >> 5, lane = tid & 31;
    int g = lane >> 2, t = lane & 3;
    int bh = blockIdx.y, b = bh >> 4, h = bh & 15;
    int q0 = blockIdx.x << 7;

    // ---- load Q tile (128 x 64 bf16 hi/lo) ----
    size_t qb = ((size_t)bh * SS + q0) * HD;
#pragma unroll
    for (int i = tid; i < 128 * 8; i += 256) {
        int r = i >> 3, c = i & 7;
        uint32_t so = SOFF(r, c);
        *(uint4*)(sm + O_QH + so) = *(const uint4*)(g_Qh + qb + r * HD + c * 8);
        *(uint4*)(sm + O_QL + so) = *(const uint4*)(g_Ql + qb + r * HD + c * 8);
    }

    // per-lane ldmatrix address components
    int qrow = w * 16 + (lane & 15);          // A-frag row (Q and P)
    int qch  = lane >> 4;                     // A-frag col-half
    int krl  = lane & 7;                      // B-frag row within n-tile (K)
    int kch  = (lane >> 3) & 1;               // B-frag col-half (K)
    int vrl  = lane & 15;                     // B-frag row (V, trans)

    float rs0 = 0.f, rs1 = 0.f;

    // =================== PASS 1: exact row sums ===================
    for (int kt = 0; kt < NKT; kt++) {
        int k0 = kt << 6;
        size_t kb = ((size_t)bh * SS + k0) * HD;
        __syncthreads();
#pragma unroll
        for (int i = tid; i < 64 * 8; i += 256) {
            int r = i >> 3, c = i & 7;
            uint32_t so = SOFF(r, c);
            *(uint4*)(sm + O_KH + so) = *(const uint4*)(g_Kh + kb + r * HD + c * 8);
            *(uint4*)(sm + O_KL + so) = *(const uint4*)(g_Kl + kb + r * HD + c * 8);
        }
        if (tid < 64)
            ((float*)(sm + O_MSK))[tid] = mask[b * SS + k0 + tid] ? 1.f : 0.f;
        __syncthreads();

        float sacc[8][4];
#pragma unroll
        for (int j = 0; j < 8; j++)
#pragma unroll
            for (int x = 0; x < 4; x++) sacc[j][x] = 0.f;

#pragma unroll
        for (int kk = 0; kk < 4; kk++) {
            uint32_t ah[4], al[4];
            LDSM4(ah, sb + O_QH + SOFF(qrow, kk * 2 + qch));
            LDSM4(al, sb + O_QL + SOFF(qrow, kk * 2 + qch));
#pragma unroll
            for (int j = 0; j < 8; j++) {
                int krow = j * 8 + krl;
                uint32_t so = SOFF(krow, kk * 2 + kch);
                uint32_t bhr[2], blr[2];
                LDSM2(bhr, sb + O_KH + so);
                LDSM2(blr, sb + O_KL + so);
                MMA_BF16(sacc[j], ah, bhr[0], bhr[1]);
                MMA_BF16(sacc[j], ah, blr[0], blr[1]);
                MMA_BF16(sacc[j], al, bhr[0], bhr[1]);
            }
        }

        const float* mk = (const float*)(sm + O_MSK);
#pragma unroll
        for (int j = 0; j < 8; j++) {
            float m0 = mk[j * 8 + t * 2], m1 = mk[j * 8 + t * 2 + 1];
            rs0 += m0 * __expf(sacc[j][0] * 0.125f) + m1 * __expf(sacc[j][1] * 0.125f);
            rs1 += m0 * __expf(sacc[j][2] * 0.125f) + m1 * __expf(sacc[j][3] * 0.125f);
        }
    }
    // quad reduce (lanes g*4..g*4+3 share rows g / g+8)
    rs0 += __shfl_xor_sync(0xffffffffu, rs0, 1);
    rs0 += __shfl_xor_sync(0xffffffffu, rs0, 2);
    rs1 += __shfl_xor_sync(0xffffffffu, rs1, 1);
    rs1 += __shfl_xor_sync(0xffffffffu, rs1, 2);
    float inv0 = 1.f / rs0, inv1 = 1.f / rs1;

    // =================== PASS 2: normalized attn + PV ===================
    float vacc[8][4];
#pragma unroll
    for (int j = 0; j < 8; j++)
#pragma unroll
        for (int x = 0; x < 4; x++) vacc[j][x] = 0.f;

    for (int kt = 0; kt < NKT; kt++) {
        int k0 = kt << 6;
        size_t kb = ((size_t)bh * SS + k0) * HD;
        __syncthreads();
#pragma unroll
        for (int i = tid; i < 64 * 8; i += 256) {
            int r = i >> 3, c = i & 7;
            uint32_t so = SOFF(r, c);
            *(uint4*)(sm + O_KH + so) = *(const uint4*)(g_Kh + kb + r * HD + c * 8);
            *(uint4*)(sm + O_KL + so) = *(const uint4*)(g_Kl + kb + r * HD + c * 8);
            *(uint4*)(sm + O_VH + so) = *(const uint4*)(g_Vh + kb + r * HD + c * 8);
            *(uint4*)(sm + O_VL + so) = *(const uint4*)(g_Vl + kb + r * HD + c * 8);
        }
        if (tid < 64)
            ((float*)(sm + O_MSK))[tid] = mask[b * SS + k0 + tid] ? 1.f : 0.f;
        __syncthreads();

        // ---- scores (recompute) ----
        float sacc[8][4];
#pragma unroll
        for (int j = 0; j < 8; j++)
#pragma unroll
            for (int x = 0; x < 4; x++) sacc[j][x] = 0.f;
#pragma unroll
        for (int kk = 0; kk < 4; kk++) {
            uint32_t ah[4], al[4];
            LDSM4(ah, sb + O_QH + SOFF(qrow, kk * 2 + qch));
            LDSM4(al, sb + O_QL + SOFF(qrow, kk * 2 + qch));
#pragma unroll
            for (int j = 0; j < 8; j++) {
                int krow = j * 8 + krl;
                uint32_t so = SOFF(krow, kk * 2 + kch);
                uint32_t bhr[2], blr[2];
                LDSM2(bhr, sb + O_KH + so);
                LDSM2(blr, sb + O_KL + so);
                MMA_BF16(sacc[j], ah, bhr[0], bhr[1]);
                MMA_BF16(sacc[j], ah, blr[0], blr[1]);
                MMA_BF16(sacc[j], al, bhr[0], bhr[1]);
            }
        }

        // ---- normalized p: write attn + build PV A-fragments in regs ----
        uint32_t phA[8][2], plA[8][2];
        const float* mk = (const float*)(sm + O_MSK);
        size_t ab = ((size_t)bh * SS + q0 + w * 16) * (size_t)SS + k0;
#pragma unroll
        for (int j = 0; j < 8; j++) {
            float m0 = mk[j * 8 + t * 2], m1 = mk[j * 8 + t * 2 + 1];
            float p0 = m0 * __expf(sacc[j][0] * 0.125f) * inv0;
            float p1 = m1 * __expf(sacc[j][1] * 0.125f) * inv0;
            float p2 = m0 * __expf(sacc[j][2] * 0.125f) * inv1;
            float p3 = m1 * __expf(sacc[j][3] * 0.125f) * inv1;
            int cc = j * 8 + t * 2;
            *(float2*)&attn[ab + (size_t)g * SS + cc]       = make_float2(p0, p1);
            *(float2*)&attn[ab + (size_t)(g + 8) * SS + cc] = make_float2(p2, p3);
            split2(p0, p1, phA[j][0], plA[j][0]);
            split2(p2, p3, phA[j][1], plA[j][1]);
        }

        // ---- PV: vacc += P @ V ----
#pragma unroll
        for (int kk2 = 0; kk2 < 4; kk2++) {
            uint32_t ah[4] = { phA[2*kk2][0], phA[2*kk2][1],
                               phA[2*kk2+1][0], phA[2*kk2+1][1] };
            uint32_t al[4] = { plA[2*kk2][0], plA[2*kk2][1],
                               plA[2*kk2+1][0], plA[2*kk2+1][1] };
            int vrow = kk2 * 16 + vrl;
#pragma unroll
            for (int nj = 0; nj < 8; nj++) {
                uint32_t so = SOFF(vrow, nj);
                uint32_t bhr[2], blr[2];
                LDSM2T(bhr, sb + O_VH + so);
                LDSM2T(blr, sb + O_VL + so);
                MMA_BF16(vacc[nj], ah, bhr[0], bhr[1]);
                MMA_BF16(vacc[nj], ah, blr[0], blr[1]);
                MMA_BF16(vacc[nj], al, bhr[0], bhr[1]);
            }
        }
    }

    // ---- epilogue: ctx (already normalized) -> [B][S][D] ----
    {
        float* cp0 = g_ctx + ((size_t)(b * SS + q0 + w * 16 + g)) * DD + h * HD;
        float* cp1 = cp0 + (size_t)8 * DD;
#pragma unroll
        for (int nj = 0; nj < 8; nj++) {
            int cc = nj * 8 + t * 2;
            *(float2*)&cp0[cc] = make_float2(vacc[nj][0], vacc[nj][1]);
            *(float2*)&cp1[cc] = make_float2(vacc[nj][2], vacc[nj][3]);
        }
    }
}

// ---------------- launch ----------------
extern "C" void kernel_launch(void* const* d_in, const int* in_sizes, int n_in,
                              void* d_out, int out_size)
{
    const float* q    = (const float*)d_in[0];
    const float* k    = (const float*)d_in[1];
    const float* v    = (const float*)d_in[2];
    const int*   mask = (const int*)  d_in[3];
    const float* Wq   = (const float*)d_in[4];
    const float* bq   = (const float*)d_in[5];
    const float* Wk   = (const float*)d_in[6];
    const float* bk   = (const float*)d_in[7];
    const float* Wv   = (const float*)d_in[8];
    const float* bv   = (const float*)d_in[9];
    const float* Wo   = (const float*)d_in[10];
    const float* bo   = (const float*)d_in[11];

    float* outx = (float*)d_out;
    float* attn = outx + X_ELEMS;

    float* pC;
    __nv_bfloat16 *pQh, *pQl, *pKh, *pKl, *pVh, *pVl;
    cudaGetSymbolAddress((void**)&pC,  g_ctx);
    cudaGetSymbolAddress((void**)&pQh, g_Qh);
    cudaGetSymbolAddress((void**)&pQl, g_Ql);
    cudaGetSymbolAddress((void**)&pKh, g_Kh);
    cudaGetSymbolAddress((void**)&pKl, g_Kl);
    cudaGetSymbolAddress((void**)&pVh, g_Vh);
    cudaGetSymbolAddress((void**)&pVl, g_Vl);

    cudaFuncSetAttribute(attn_mma,
                         cudaFuncAttributeMaxDynamicSharedMemorySize, ATT_SMEM);

    dim3 gg(DD / 128, MROWS / 128), bt(256);
    sgemm128<<<gg, bt>>>(q, Wq, bq, nullptr, pQh, pQl, 0);
    sgemm128<<<gg, bt>>>(k, Wk, bk, nullptr, pKh, pKl, 0);
    sgemm128<<<gg, bt>>>(v, Wv, bv, nullptr, pVh, pVl, 0);

    attn_mma<<<dim3(SS / 128, BB * HH), 256, ATT_SMEM>>>(mask, attn);

    sgemm128<<<gg, bt>>>(pC, Wo, bo, outx, nullptr, nullptr, 1);
}